// round 1
// baseline (speedup 1.0000x reference)
#include <cuda_runtime.h>

#define TABLES   4608
#define OC_N     32
#define TPO      144      // tables per output channel
#define IC_N     16
#define PH       34
#define PW       34
#define TILE_ELEMS (IC_N*PH*PW)   // 18496 floats = 73984 B
#define BATCH    8
#define NTHREADS 256
#define PPT      4        // positions per thread (256*4 = 1024 = 32x32)

// Persistent scratch (no allocations allowed)
__device__ int2   g_offs[TABLES];
__device__ float4 g_coef[TABLES];
__device__ float  g_base[OC_N];

// ---------------------------------------------------------------------------
// Per-table precompute: bilinear coefficients + fused gather offsets.
// out_t = a + b*x0 + c*x1 + d*x0*x1   (a folded into g_base per-oc)
// ---------------------------------------------------------------------------
__global__ void precompute_kernel(const float* __restrict__ w,
                                  const int*  __restrict__ mc,
                                  const int*  __restrict__ mkh,
                                  const int*  __restrict__ mkw) {
    int t = blockIdx.x * blockDim.x + threadIdx.x;
    if (t >= TABLES) return;
    float w0 = w[4*t+0], w1 = w[4*t+1], w2 = w[4*t+2], w3 = w[4*t+3];
    float4 c;
    c.x = 0.25f * (-w0 + w1 - w2 + w3);   // coeff of x0
    c.y = 0.25f * (-w0 - w1 + w2 + w3);   // coeff of x1
    c.z = 0.25f * ( w0 - w1 - w2 + w3);   // coeff of x0*x1
    c.w = 0.25f * ( w0 + w1 + w2 + w3);   // constant (unused in inner loop)
    g_coef[t] = c;
    int m0 = 2*t, m1 = 2*t + 1;
    g_offs[t] = make_int2(mc[m0]*(PH*PW) + mkh[m0]*PW + mkw[m0],
                          mc[m1]*(PH*PW) + mkh[m1]*PW + mkw[m1]);
}

// Per-oc constant term: A_oc = sum over the oc's 144 tables of (w0+w1+w2+w3)/4
__global__ void base_kernel(const float* __restrict__ w) {
    int warp = threadIdx.x >> 5;     // warp == oc (32 warps)
    int lane = threadIdx.x & 31;
    float s = 0.0f;
    for (int i = lane; i < TPO; i += 32) {
        int t = warp * TPO + i;
        s += w[4*t+0] + w[4*t+1] + w[4*t+2] + w[4*t+3];
    }
    #pragma unroll
    for (int d = 16; d; d >>= 1) s += __shfl_xor_sync(0xffffffffu, s, d);
    if (lane == 0) g_base[warp] = 0.25f * s;
}

// ---------------------------------------------------------------------------
// Main kernel: one block per (batch, oc). Padded image for the batch lives in
// shared memory; gathers are conflict-free (consecutive lanes -> consecutive
// addresses). Inner loop: 144 tables x 4 positions, 2 LDS + 3 FMA per eval.
// ---------------------------------------------------------------------------
extern __shared__ float smem[];

__global__ void __launch_bounds__(NTHREADS)
lutconv_kernel(const float* __restrict__ inp, float* __restrict__ out) {
    const int b  = blockIdx.x >> 5;
    const int oc = blockIdx.x & 31;

    float*  tile  = smem;                                   // [IC_N*PH*PW]
    int2*   soff  = (int2*)(smem + TILE_ELEMS);             // [TPO]
    float4* scoef = (float4*)((char*)soff + TPO*sizeof(int2)); // [TPO], 16B aligned

    const int tid = threadIdx.x;

    // Stage per-oc table coefficients
    if (tid < TPO) {
        soff[tid]  = g_offs[oc*TPO + tid];
        scoef[tid] = g_coef[oc*TPO + tid];
    }

    // Stage padded image for batch b: tile[c][py][px], zero halo
    const float* ib = inp + (size_t)b * (IC_N*32*32);
    for (int i = tid; i < TILE_ELEMS; i += NTHREADS) {
        int c  = i / (PH*PW);
        int r  = i - c*(PH*PW);
        int py = r / PW;
        int px = r - py*PW;
        float v = 0.0f;
        if (py >= 1 && py <= 32 && px >= 1 && px <= 32)
            v = ib[(c*32 + (py-1))*32 + (px-1)];
        tile[i] = v;
    }
    __syncthreads();

    const float A = g_base[oc];
    float acc0 = A, acc1 = A, acc2 = A, acc3 = A;

    // positions handled: pos_p = p*256 + tid  -> y = tid/32 + 8p, x = tid%32
    const int a0 = (tid >> 5) * PW + (tid & 31);
    const int S  = 8 * PW;   // 272: address step per position group

    #pragma unroll 4
    for (int t = 0; t < TPO; ++t) {
        const int2   o = soff[t];
        const float4 c = scoef[t];
        {
            float x0 = tile[o.x + a0],         x1 = tile[o.y + a0];
            float tmp = fmaf(c.z, x1, c.x);
            acc0 = fmaf(x0, tmp, acc0);
            acc0 = fmaf(c.y, x1, acc0);
        }
        {
            float x0 = tile[o.x + a0 + S],     x1 = tile[o.y + a0 + S];
            float tmp = fmaf(c.z, x1, c.x);
            acc1 = fmaf(x0, tmp, acc1);
            acc1 = fmaf(c.y, x1, acc1);
        }
        {
            float x0 = tile[o.x + a0 + 2*S],   x1 = tile[o.y + a0 + 2*S];
            float tmp = fmaf(c.z, x1, c.x);
            acc2 = fmaf(x0, tmp, acc2);
            acc2 = fmaf(c.y, x1, acc2);
        }
        {
            float x0 = tile[o.x + a0 + 3*S],   x1 = tile[o.y + a0 + 3*S];
            float tmp = fmaf(c.z, x1, c.x);
            acc3 = fmaf(x0, tmp, acc3);
            acc3 = fmaf(c.y, x1, acc3);
        }
    }

    float* ob = out + ((size_t)(b*OC_N + oc)) * 1024;
    ob[tid]        = acc0;
    ob[tid + 256]  = acc1;
    ob[tid + 512]  = acc2;
    ob[tid + 768]  = acc3;
}

// ---------------------------------------------------------------------------
extern "C" void kernel_launch(void* const* d_in, const int* in_sizes, int n_in,
                              void* d_out, int out_size) {
    const float* inp = (const float*)d_in[0];
    const float* w   = (const float*)d_in[1];
    const int*   mc  = (const int*)d_in[2];
    const int*   mkh = (const int*)d_in[3];
    const int*   mkw = (const int*)d_in[4];
    float*       out = (float*)d_out;

    precompute_kernel<<<(TABLES + 255)/256, 256>>>(w, mc, mkh, mkw);
    base_kernel<<<1, 1024>>>(w);

    const int smem_bytes = TILE_ELEMS*(int)sizeof(float)
                         + TPO*(int)sizeof(int2) + TPO*(int)sizeof(float4); // 77440
    cudaFuncSetAttribute(lutconv_kernel,
                         cudaFuncAttributeMaxDynamicSharedMemorySize, smem_bytes);
    lutconv_kernel<<<BATCH*OC_N, NTHREADS, smem_bytes>>>(inp, out);
}

// round 2
// speedup vs baseline: 1.2653x; 1.2653x over previous
#include <cuda_runtime.h>

#define TABLES     4608
#define OC_N       32
#define TPO        144            // tables per output channel
#define IC_N       16
#define PH         34
#define PW         34
#define CH_STRIDE  (PH*PW)        // 1156
#define TILE_ELEMS (IC_N*CH_STRIDE)   // 18496 floats = 73984 B
#define NTHREADS   256
#define ROWSTEP    (8*PW)         // 272: address step between position groups

// Single fused kernel: one block per (batch, oc).
//   out[b,oc,y,x] = A_oc + sum_t [ b_t*x0 + c_t*x1 + d_t*x0*x1 ]
// with x0,x1 gathered from the padded image tile in shared memory.
// Per-table payload packed into ONE float4 broadcast: {off0|off1<<16, b, c, d}.
extern __shared__ float smem[];

__global__ void __launch_bounds__(NTHREADS)
lutconv_fused(const float*  __restrict__ inp,
              const float4* __restrict__ w4,
              const int*    __restrict__ mc,
              const int*    __restrict__ mkh,
              const int*    __restrict__ mkw,
              float*        __restrict__ out) {
    const int b   = blockIdx.x >> 5;
    const int oc  = blockIdx.x & 31;
    const int tid = threadIdx.x;

    float*  tile  = smem;                              // [TILE_ELEMS]
    float4* scoef = (float4*)(smem + TILE_ELEMS);      // [TPO] (73984 % 16 == 0)
    float*  scw   = (float*)(scoef + TPO);             // [TPO] per-table constant
    float*  sA    = scw + TPO;                         // [1]

    // --- Fused per-table precompute (bilinear coeffs + packed gather offsets)
    if (tid < TPO) {
        const int t = oc*TPO + tid;
        const float4 wv = w4[t];
        const float bco = 0.25f * (-wv.x + wv.y - wv.z + wv.w);
        const float cco = 0.25f * (-wv.x - wv.y + wv.z + wv.w);
        const float dco = 0.25f * ( wv.x - wv.y - wv.z + wv.w);
        const float aco = 0.25f * ( wv.x + wv.y + wv.z + wv.w);
        const int m0 = 2*t;
        const unsigned off0 = (unsigned)(mc[m0  ]*CH_STRIDE + mkh[m0  ]*PW + mkw[m0  ]);
        const unsigned off1 = (unsigned)(mc[m0+1]*CH_STRIDE + mkh[m0+1]*PW + mkw[m0+1]);
        float4 p;
        p.x = __uint_as_float(off0 | (off1 << 16));
        p.y = bco; p.z = cco; p.w = dco;
        scoef[tid] = p;
        scw[tid]   = aco;
    }

    // --- Stage padded image for batch b (zero halo), layout [c][py][px]
    const float* ib = inp + (size_t)b * (IC_N*32*32);
    for (int i = tid; i < TILE_ELEMS; i += NTHREADS) {
        const int c  = i / CH_STRIDE;
        const int r  = i - c*CH_STRIDE;
        const int py = r / PW;
        const int px = r - py*PW;
        float v = 0.0f;
        if (py >= 1 && py <= 32 && px >= 1 && px <= 32)
            v = ib[(c*32 + (py-1))*32 + (px-1)];
        tile[i] = v;
    }
    __syncthreads();

    // --- Per-oc constant term A (one warp reduces the 144 per-table constants)
    if (tid < 32) {
        float s = scw[tid] + scw[tid+32] + scw[tid+64] + scw[tid+96]
                + (tid < (TPO - 128) ? scw[tid+128] : 0.0f);
        #pragma unroll
        for (int d = 16; d; d >>= 1) s += __shfl_xor_sync(0xffffffffu, s, d);
        if (tid == 0) *sA = s;
    }
    __syncthreads();

    // --- Main loop: 144 tables x 4 positions/thread, 2 LDS + 3 FMA per eval
    float acc0 = 0.f, acc1 = 0.f, acc2 = 0.f, acc3 = 0.f;
    const int a0 = (tid >> 5) * PW + (tid & 31);   // y = tid/32, x = tid%32
    const int a1 = a0 + ROWSTEP;
    const int a2 = a0 + 2*ROWSTEP;
    const int a3 = a0 + 3*ROWSTEP;

    #pragma unroll 8
    for (int t = 0; t < TPO; ++t) {
        const float4 p = scoef[t];
        const unsigned u = __float_as_uint(p.x);
        const int o0 = (int)(u & 0xffffu);
        const int o1 = (int)(u >> 16);
        {
            const float x0 = tile[o0 + a0], x1 = tile[o1 + a0];
            const float t1 = fmaf(p.w, x1, p.y);
            acc0 = fmaf(x0, t1, acc0);
            acc0 = fmaf(p.z, x1, acc0);
        }
        {
            const float x0 = tile[o0 + a1], x1 = tile[o1 + a1];
            const float t1 = fmaf(p.w, x1, p.y);
            acc1 = fmaf(x0, t1, acc1);
            acc1 = fmaf(p.z, x1, acc1);
        }
        {
            const float x0 = tile[o0 + a2], x1 = tile[o1 + a2];
            const float t1 = fmaf(p.w, x1, p.y);
            acc2 = fmaf(x0, t1, acc2);
            acc2 = fmaf(p.z, x1, acc2);
        }
        {
            const float x0 = tile[o0 + a3], x1 = tile[o1 + a3];
            const float t1 = fmaf(p.w, x1, p.y);
            acc3 = fmaf(x0, t1, acc3);
            acc3 = fmaf(p.z, x1, acc3);
        }
    }

    const float A = *sA;
    float* ob = out + ((size_t)(b*OC_N + oc)) * 1024;
    ob[tid      ] = acc0 + A;
    ob[tid + 256] = acc1 + A;
    ob[tid + 512] = acc2 + A;
    ob[tid + 768] = acc3 + A;
}

// ---------------------------------------------------------------------------
extern "C" void kernel_launch(void* const* d_in, const int* in_sizes, int n_in,
                              void* d_out, int out_size) {
    const float*  inp = (const float*)d_in[0];
    const float4* w4  = (const float4*)d_in[1];
    const int*    mc  = (const int*)d_in[2];
    const int*    mkh = (const int*)d_in[3];
    const int*    mkw = (const int*)d_in[4];
    float*        out = (float*)d_out;

    const int smem_bytes = TILE_ELEMS*(int)sizeof(float)           // tile
                         + TPO*(int)sizeof(float4)                 // packed coefs
                         + (TPO + 1)*(int)sizeof(float);           // scw + sA
    cudaFuncSetAttribute(lutconv_fused,
                         cudaFuncAttributeMaxDynamicSharedMemorySize, smem_bytes);
    lutconv_fused<<<8*OC_N, NTHREADS, smem_bytes>>>(inp, w4, mc, mkh, mkw, out);
}

// round 3
// speedup vs baseline: 1.3908x; 1.0992x over previous
#include <cuda_runtime.h>

#define TABLES     4608
#define OC_N       32
#define TPO        144            // tables per output channel
#define IC_N       16
#define PH         34
#define PW         34
#define CH_STRIDE  (PH*PW)        // 1156
#define TILE_ELEMS (IC_N*CH_STRIDE)   // 18496 floats = 73984 B
#define NTHREADS   256
#define S          (8*PW)         // 272: address step between position groups

// Fused kernel: one block per (batch, oc).
//   out[b,oc,y,x] = A_oc + sum_t [ b_t*x0 + c_t*x1 + d_t*x0*x1 ]
// x0,x1 gathered from the padded image tile in shared memory (conflict-free:
// consecutive lanes hit consecutive addresses).
// Per-table payload: ONE float4 broadcast {off0|off1<<16, b, c, d}.
extern __shared__ float smem[];

__global__ void __launch_bounds__(NTHREADS, 2)
lutconv_fused(const float*  __restrict__ inp,
              const float4* __restrict__ w4,
              const int*    __restrict__ mc,
              const int*    __restrict__ mkh,
              const int*    __restrict__ mkw,
              float*        __restrict__ out) {
    const int b   = blockIdx.x >> 5;
    const int oc  = blockIdx.x & 31;
    const int tid = threadIdx.x;

    float*  tile  = smem;                              // [TILE_ELEMS]
    float4* scoef = (float4*)(smem + TILE_ELEMS);      // [TPO]
    float*  scw   = (float*)(scoef + TPO);             // [TPO]
    float*  sA    = scw + TPO;                         // [1]

    // --- Per-table precompute: bilinear coeffs + packed gather offsets
    if (tid < TPO) {
        const int t = oc*TPO + tid;
        const float4 wv = w4[t];
        const float bco = 0.25f * (-wv.x + wv.y - wv.z + wv.w);
        const float cco = 0.25f * (-wv.x - wv.y + wv.z + wv.w);
        const float dco = 0.25f * ( wv.x - wv.y - wv.z + wv.w);
        const float aco = 0.25f * ( wv.x + wv.y + wv.z + wv.w);
        const int m0 = 2*t;
        const unsigned off0 = (unsigned)(mc[m0  ]*CH_STRIDE + mkh[m0  ]*PW + mkw[m0  ]);
        const unsigned off1 = (unsigned)(mc[m0+1]*CH_STRIDE + mkh[m0+1]*PW + mkw[m0+1]);
        float4 p;
        p.x = __uint_as_float(off0 | (off1 << 16));
        p.y = bco; p.z = cco; p.w = dco;
        scoef[tid] = p;
        scw[tid]   = aco;
    }

    // --- Stage padded tile: vectorized zero-fill, then float4 interior copy.
    {
        const float4 z4 = make_float4(0.f, 0.f, 0.f, 0.f);
        float4* t4 = (float4*)tile;
        #pragma unroll
        for (int i = tid; i < TILE_ELEMS/4; i += NTHREADS) t4[i] = z4;
    }
    __syncthreads();
    {
        const float4* ib4 = (const float4*)(inp + (size_t)b * (IC_N*32*32));
        #pragma unroll
        for (int i = tid; i < 4096; i += NTHREADS) {    // 16 iterations
            const float4 v = ib4[i];
            const int j = i << 2;                       // element index
            const int c = j >> 10;                      // channel
            const int y = (j >> 5) & 31;                // row
            const int x = j & 31;                       // col (multiple of 4)
            float* dst = tile + c*CH_STRIDE + (y+1)*PW + x + 1;
            dst[0] = v.x; dst[1] = v.y; dst[2] = v.z; dst[3] = v.w;
        }
    }
    __syncthreads();

    // --- Per-oc constant term A
    if (tid < 32) {
        float s = scw[tid] + scw[tid+32] + scw[tid+64] + scw[tid+96]
                + (tid < (TPO - 128) ? scw[tid+128] : 0.0f);
        #pragma unroll
        for (int d = 16; d; d >>= 1) s += __shfl_xor_sync(0xffffffffu, s, d);
        if (tid == 0) *sA = s;
    }
    __syncthreads();

    // --- Main loop: 2 tables per step, all 16 loads batched before FMAs.
    float acc0 = 0.f, acc1 = 0.f, acc2 = 0.f, acc3 = 0.f;
    const float* base = tile + ((tid >> 5) * PW + (tid & 31));

    #pragma unroll 2
    for (int t = 0; t < TPO; t += 2) {
        const float4 pa = scoef[t];
        const float4 pb = scoef[t+1];
        const unsigned ua = __float_as_uint(pa.x);
        const unsigned ub = __float_as_uint(pb.x);
        const float* A0 = base + (ua & 0xffffu);
        const float* A1 = base + (ua >> 16);
        const float* B0 = base + (ub & 0xffffu);
        const float* B1 = base + (ub >> 16);

        const float xa00 = A0[0],   xa10 = A1[0];
        const float xa01 = A0[S],   xa11 = A1[S];
        const float xa02 = A0[2*S], xa12 = A1[2*S];
        const float xa03 = A0[3*S], xa13 = A1[3*S];
        const float xb00 = B0[0],   xb10 = B1[0];
        const float xb01 = B0[S],   xb11 = B1[S];
        const float xb02 = B0[2*S], xb12 = B1[2*S];
        const float xb03 = B0[3*S], xb13 = B1[3*S];

        acc0 = fmaf(xa00, fmaf(pa.w, xa10, pa.y), fmaf(pa.z, xa10, acc0));
        acc1 = fmaf(xa01, fmaf(pa.w, xa11, pa.y), fmaf(pa.z, xa11, acc1));
        acc2 = fmaf(xa02, fmaf(pa.w, xa12, pa.y), fmaf(pa.z, xa12, acc2));
        acc3 = fmaf(xa03, fmaf(pa.w, xa13, pa.y), fmaf(pa.z, xa13, acc3));
        acc0 = fmaf(xb00, fmaf(pb.w, xb10, pb.y), fmaf(pb.z, xb10, acc0));
        acc1 = fmaf(xb01, fmaf(pb.w, xb11, pb.y), fmaf(pb.z, xb11, acc1));
        acc2 = fmaf(xb02, fmaf(pb.w, xb12, pb.y), fmaf(pb.z, xb12, acc2));
        acc3 = fmaf(xb03, fmaf(pb.w, xb13, pb.y), fmaf(pb.z, xb13, acc3));
    }

    const float A = *sA;
    float* ob = out + ((size_t)(b*OC_N + oc)) * 1024;
    ob[tid      ] = acc0 + A;
    ob[tid + 256] = acc1 + A;
    ob[tid + 512] = acc2 + A;
    ob[tid + 768] = acc3 + A;
}

// ---------------------------------------------------------------------------
extern "C" void kernel_launch(void* const* d_in, const int* in_sizes, int n_in,
                              void* d_out, int out_size) {
    const float*  inp = (const float*)d_in[0];
    const float4* w4  = (const float4*)d_in[1];
    const int*    mc  = (const int*)d_in[2];
    const int*    mkh = (const int*)d_in[3];
    const int*    mkw = (const int*)d_in[4];
    float*        out = (float*)d_out;

    const int smem_bytes = TILE_ELEMS*(int)sizeof(float)
                         + TPO*(int)sizeof(float4)
                         + (TPO + 1)*(int)sizeof(float);
    cudaFuncSetAttribute(lutconv_fused,
                         cudaFuncAttributeMaxDynamicSharedMemorySize, smem_bytes);
    lutconv_fused<<<8*OC_N, NTHREADS, smem_bytes>>>(inp, w4, mc, mkh, mkw, out);
}